// round 2
// baseline (speedup 1.0000x reference)
#include <cuda_runtime.h>
#include <cuda_bf16.h>
#include <cstdint>

#define B_  16
#define N_  1024
#define S_  256
#define D_  1024
#define HQ  16
#define HKV 8
#define HD  64
#define KVE 512

// ---------------- scratch (device globals; no cudaMalloc allowed) ----------
__device__ __nv_bfloat16 g_xq [(size_t)B_*N_*D_];
__device__ __nv_bfloat16 g_yq [(size_t)B_*S_*D_];
__device__ __nv_bfloat16 g_a2q[(size_t)B_*N_*D_];
__device__ __nv_bfloat16 g_wqt[D_*D_];
__device__ __nv_bfloat16 g_wkt[KVE*D_];
__device__ __nv_bfloat16 g_wvt[KVE*D_];
__device__ __nv_bfloat16 g_wot[D_*D_];
__device__ float  g_q  [(size_t)B_*N_*D_];
__device__ float  g_k  [(size_t)B_*S_*KVE];
__device__ float  g_v  [(size_t)B_*S_*KVE];
__device__ float  g_att[(size_t)B_*N_*D_];
__device__ float  g_rfx[B_*N_];
__device__ float  g_rfy[B_*S_];
__device__ float  g_rf2[B_*N_];
__device__ double g_part[4*256];
__device__ double g_wsum[4];

// ---------------- block reductions (256 threads) ----------------------------
__device__ __forceinline__ float block_sum(float v, float* sbuf) {
    #pragma unroll
    for (int o = 16; o; o >>= 1) v += __shfl_xor_sync(0xffffffffu, v, o);
    int w = threadIdx.x >> 5, l = threadIdx.x & 31;
    if (!l) sbuf[w] = v;
    __syncthreads();
    if (threadIdx.x < 8) {
        v = sbuf[threadIdx.x];
        #pragma unroll
        for (int o = 4; o; o >>= 1) v += __shfl_xor_sync(0x000000ffu, v, o);
        if (!threadIdx.x) sbuf[0] = v;
    }
    __syncthreads();
    v = sbuf[0];
    __syncthreads();
    return v;
}
__device__ __forceinline__ float block_max(float v, float* sbuf) {
    #pragma unroll
    for (int o = 16; o; o >>= 1) v = fmaxf(v, __shfl_xor_sync(0xffffffffu, v, o));
    int w = threadIdx.x >> 5, l = threadIdx.x & 31;
    if (!l) sbuf[w] = v;
    __syncthreads();
    if (threadIdx.x < 8) {
        v = sbuf[threadIdx.x];
        #pragma unroll
        for (int o = 4; o; o >>= 1) v = fmaxf(v, __shfl_xor_sync(0x000000ffu, v, o));
        if (!threadIdx.x) sbuf[0] = v;
    }
    __syncthreads();
    v = sbuf[0];
    __syncthreads();
    return v;
}

// ---------------- weight prep ----------------------------------------------
__global__ void __launch_bounds__(256) absmean_kernel(const float* __restrict__ w, int n, int slot) {
    __shared__ float sbuf[8];
    float s = 0.f;
    for (int i = blockIdx.x * 256 + threadIdx.x; i < n; i += 256 * 256)
        s += fabsf(w[i]);
    s = block_sum(s, sbuf);
    if (!threadIdx.x) g_part[slot * 256 + blockIdx.x] = (double)s;
}
__global__ void __launch_bounds__(256) reduce_kernel() {
    __shared__ double sd[256];
    int slot = blockIdx.x;
    sd[threadIdx.x] = g_part[slot * 256 + threadIdx.x];
    __syncthreads();
    for (int o = 128; o; o >>= 1) {
        if (threadIdx.x < o) sd[threadIdx.x] += sd[threadIdx.x + o];
        __syncthreads();
    }
    if (!threadIdx.x) g_wsum[slot] = sd[0];
}
__global__ void __launch_bounds__(256) wquant_kernel(const float* __restrict__ w, int n,
                                                     int slot, double invcnt) {
    __nv_bfloat16* out = slot == 0 ? g_wqt : slot == 1 ? g_wkt : slot == 2 ? g_wvt : g_wot;
    float mean  = (float)(g_wsum[slot] * invcnt);
    float scale = 1.0f / fmaxf(mean, 1e-5f);
    for (int i = blockIdx.x * 256 + threadIdx.x; i < n; i += gridDim.x * 256) {
        float t = fminf(fmaxf(rintf(w[i] * scale), -1.f), 1.f);
        out[i] = __float2bfloat16(t);
    }
}

// ---------------- activation quant: rms_norm + absmax int8 -----------------
__global__ void __launch_bounds__(256) act_quant_kernel(const float* __restrict__ X, int which) {
    __shared__ float sbuf[8];
    __nv_bfloat16* Q  = which ? g_yq : g_xq;
    float*         RF = which ? g_rfy : g_rfx;
    size_t row = blockIdx.x;
    int t = threadIdx.x;
    float4 xv = ((const float4*)(X + row * D_))[t];

    float ssq = xv.x*xv.x + xv.y*xv.y + xv.z*xv.z + xv.w*xv.w;
    ssq = block_sum(ssq, sbuf);
    float r = 1.0f / sqrtf(ssq * (1.0f/1024.0f) + 1e-6f);

    float am = fmaxf(fmaxf(fabsf(xv.x), fabsf(xv.y)), fmaxf(fabsf(xv.z), fabsf(xv.w)));
    am = block_max(am, sbuf) * r;
    float sc = 127.0f / fmaxf(am, 1e-5f);

    __nv_bfloat16* qr = Q + row * D_ + t * 4;
    qr[0] = __float2bfloat16(fminf(fmaxf(rintf((xv.x*r)*sc), -128.f), 127.f));
    qr[1] = __float2bfloat16(fminf(fmaxf(rintf((xv.y*r)*sc), -128.f), 127.f));
    qr[2] = __float2bfloat16(fminf(fmaxf(rintf((xv.z*r)*sc), -128.f), 127.f));
    qr[3] = __float2bfloat16(fminf(fmaxf(rintf((xv.w*r)*sc), -128.f), 127.f));
    if (!t) RF[row] = 1.0f / sc;
}

// ---------------- fused LayerNorm + rms_norm + act_quant -------------------
__global__ void __launch_bounds__(256) ln_quant_kernel(const float* __restrict__ gamma,
                                                       const float* __restrict__ beta) {
    __shared__ float sbuf[8];
    size_t row = blockIdx.x;
    int t = threadIdx.x;
    float4 xv = ((const float4*)(g_att + row * D_))[t];

    float mu = block_sum(xv.x + xv.y + xv.z + xv.w, sbuf) * (1.0f/1024.0f);
    float d0 = xv.x-mu, d1 = xv.y-mu, d2 = xv.z-mu, d3 = xv.w-mu;
    float var = block_sum(d0*d0 + d1*d1 + d2*d2 + d3*d3, sbuf) * (1.0f/1024.0f);
    float rs = 1.0f / sqrtf(var + 1e-5f);

    float4 gv = ((const float4*)gamma)[t];
    float4 bv = ((const float4*)beta)[t];
    float y0 = (d0*rs)*gv.x + bv.x, y1 = (d1*rs)*gv.y + bv.y;
    float y2 = (d2*rs)*gv.z + bv.z, y3 = (d3*rs)*gv.w + bv.w;

    float m2 = block_sum(y0*y0 + y1*y1 + y2*y2 + y3*y3, sbuf) * (1.0f/1024.0f);
    float r2 = 1.0f / sqrtf(m2 + 1e-6f);

    float am = fmaxf(fmaxf(fabsf(y0), fabsf(y1)), fmaxf(fabsf(y2), fabsf(y3)));
    am = block_max(am, sbuf) * r2;
    float sc = 127.0f / fmaxf(am, 1e-5f);

    __nv_bfloat16* qr = g_a2q + row * D_ + t * 4;
    qr[0] = __float2bfloat16(fminf(fmaxf(rintf((y0*r2)*sc), -128.f), 127.f));
    qr[1] = __float2bfloat16(fminf(fmaxf(rintf((y1*r2)*sc), -128.f), 127.f));
    qr[2] = __float2bfloat16(fminf(fmaxf(rintf((y2*r2)*sc), -128.f), 127.f));
    qr[3] = __float2bfloat16(fminf(fmaxf(rintf((y3*r2)*sc), -128.f), 127.f));
    if (!t) g_rf2[row] = 1.0f / sc;
}

// ---------------- exact integer GEMM via bf16 MMA --------------------------
__device__ __forceinline__ void ldsm4(uint32_t (&r)[4], uint32_t a) {
    asm volatile("ldmatrix.sync.aligned.m8n8.x4.shared.b16 {%0,%1,%2,%3}, [%4];"
                 : "=r"(r[0]), "=r"(r[1]), "=r"(r[2]), "=r"(r[3]) : "r"(a));
}
__device__ __forceinline__ void mma_bf16(float (&d)[4], const uint32_t (&a)[4],
                                         uint32_t b0, uint32_t b1) {
    asm volatile("mma.sync.aligned.m16n8k16.row.col.f32.bf16.bf16.f32 "
                 "{%0,%1,%2,%3}, {%4,%5,%6,%7}, {%8,%9}, {%0,%1,%2,%3};"
                 : "+f"(d[0]), "+f"(d[1]), "+f"(d[2]), "+f"(d[3])
                 : "r"(a[0]), "r"(a[1]), "r"(a[2]), "r"(a[3]), "r"(b0), "r"(b1));
}

// C[m,n] = (sum_k A[m,k]*W[n,k]) * rowf[m] * max(mean|w|,1e-5) * extra
__device__ __forceinline__ void gemm_core(const __nv_bfloat16* __restrict__ A,
                                          const __nv_bfloat16* __restrict__ W,
                                          float* __restrict__ C,
                                          const float* __restrict__ rowf,
                                          int slot, double invcnt,
                                          float extra, int Nn, int K) {
    __shared__ __align__(16) __nv_bfloat16 sA[128 * 40];
    __shared__ __align__(16) __nv_bfloat16 sB[128 * 40];
    int tid = threadIdx.x;
    int lane = tid & 31, w = tid >> 5;
    int warpM = w & 1, warpN = w >> 1;            // 2 x 4 warps -> 64x32 per warp
    int m0 = blockIdx.y * 128, n0 = blockIdx.x * 128;

    float acc[4][4][4];
    #pragma unroll
    for (int a = 0; a < 4; a++)
        #pragma unroll
        for (int b = 0; b < 4; b++)
            #pragma unroll
            for (int c = 0; c < 4; c++) acc[a][b][c] = 0.f;

    uint32_t sAb = (uint32_t)__cvta_generic_to_shared(sA);
    uint32_t sBb = (uint32_t)__cvta_generic_to_shared(sB);
    int aRow = warpM * 64 + (lane & 15);
    int aCol = (lane >> 4) << 3;
    int bRow = warpN * 32 + ((lane & 16) >> 1) + (lane & 7);
    int bCol = lane & 8;

    for (int k0 = 0; k0 < K; k0 += 32) {
        #pragma unroll
        for (int i = 0; i < 2; i++) {
            int idx = tid + i * 256;
            int r = idx >> 2, sg = idx & 3;
            *(uint4*)(sA + r * 40 + sg * 8) =
                *(const uint4*)(A + (size_t)(m0 + r) * K + k0 + sg * 8);
            *(uint4*)(sB + r * 40 + sg * 8) =
                *(const uint4*)(W + (size_t)(n0 + r) * K + k0 + sg * 8);
        }
        __syncthreads();
        #pragma unroll
        for (int ks = 0; ks < 32; ks += 16) {
            uint32_t af[4][4];
            #pragma unroll
            for (int mi = 0; mi < 4; mi++)
                ldsm4(af[mi], sAb + (uint32_t)(((aRow + mi * 16) * 40 + ks + aCol) * 2));
            uint32_t bf[2][4];
            #pragma unroll
            for (int nb = 0; nb < 2; nb++)
                ldsm4(bf[nb], sBb + (uint32_t)(((bRow + nb * 16) * 40 + ks + bCol) * 2));
            #pragma unroll
            for (int mi = 0; mi < 4; mi++)
                #pragma unroll
                for (int ni = 0; ni < 4; ni++)
                    mma_bf16(acc[mi][ni], af[mi],
                             bf[ni >> 1][(ni & 1) * 2], bf[ni >> 1][(ni & 1) * 2 + 1]);
        }
        __syncthreads();
    }

    float wf = fmaxf((float)(g_wsum[slot] * invcnt), 1e-5f);
    float sgl = wf * extra;
    #pragma unroll
    for (int mi = 0; mi < 4; mi++) {
        int m = m0 + warpM * 64 + mi * 16 + (lane >> 2);
        float f0 = rowf[m] * sgl, f1 = rowf[m + 8] * sgl;
        #pragma unroll
        for (int ni = 0; ni < 4; ni++) {
            int n = n0 + warpN * 32 + ni * 8 + (lane & 3) * 2;
            *(float2*)(C + (size_t)m * Nn + n) =
                make_float2(acc[mi][ni][0] * f0, acc[mi][ni][1] * f0);
            *(float2*)(C + (size_t)(m + 8) * Nn + n) =
                make_float2(acc[mi][ni][2] * f1, acc[mi][ni][3] * f1);
        }
    }
}

__global__ void __launch_bounds__(256) gemm_q_kernel() {
    gemm_core(g_xq, g_wqt, g_q, g_rfx, 0, 1.0/(1024.0*1024.0), 0.125f, D_, D_);
}
__global__ void __launch_bounds__(256) gemm_k_kernel() {
    gemm_core(g_yq, g_wkt, g_k, g_rfy, 1, 1.0/(512.0*1024.0), 1.0f, KVE, D_);
}
__global__ void __launch_bounds__(256) gemm_v_kernel() {
    gemm_core(g_yq, g_wvt, g_v, g_rfy, 2, 1.0/(512.0*1024.0), 1.0f, KVE, D_);
}
__global__ void __launch_bounds__(256) gemm_o_kernel(float* __restrict__ out) {
    gemm_core(g_a2q, g_wot, out, g_rf2, 3, 1.0/(1024.0*1024.0), 1.0f, D_, D_);
}

// ---------------- attention (fp32, 16 q rows / block) ----------------------
__global__ void __launch_bounds__(256) attn_kernel() {
    __shared__ float sK[64][65];
    __shared__ float sS[16][256];
    __shared__ float sQ[16][64];
    int tid = threadIdx.x, lane = tid & 31, w = tid >> 5;
    int blk = blockIdx.x;
    int ntile = blk & 63;            // N_/16 = 64
    int qh    = (blk >> 6) & 15;
    int b     = blk >> 10;
    int h     = qh >> 1;

    const float* Qb = g_q  + ((size_t)(b * N_ + ntile * 16)) * D_ + qh * HD;
    const float* Kb = g_k  + ((size_t)(b * S_)) * KVE + h * HD;
    const float* Vb = g_v  + ((size_t)(b * S_)) * KVE + h * HD;

    for (int i = tid; i < 16 * 64; i += 256) {
        int r = i >> 6, d = i & 63;
        sQ[r][d] = Qb[(size_t)r * D_ + d];
    }
    int r0 = w * 2, r1 = w * 2 + 1;

    for (int st = 0; st < 4; st++) {
        __syncthreads();
        for (int i = tid; i < 64 * 64; i += 256) {
            int r = i >> 6, d = i & 63;
            sK[r][d] = Kb[(size_t)(st * 64 + r) * KVE + d];
        }
        __syncthreads();
        float a00 = 0, a01 = 0, a10 = 0, a11 = 0;
        #pragma unroll 8
        for (int d = 0; d < 64; d++) {
            float q0 = sQ[r0][d], q1 = sQ[r1][d];
            float k0 = sK[lane][d], k1 = sK[lane + 32][d];
            a00 += q0 * k0; a01 += q0 * k1;
            a10 += q1 * k0; a11 += q1 * k1;
        }
        sS[r0][st * 64 + lane]      = a00;
        sS[r0][st * 64 + 32 + lane] = a01;
        sS[r1][st * 64 + lane]      = a10;
        sS[r1][st * 64 + 32 + lane] = a11;
    }
    __syncwarp();

    #pragma unroll
    for (int rr = 0; rr < 2; rr++) {
        int r = w * 2 + rr;
        float e[8];
        float mx = -1e30f;
        #pragma unroll
        for (int j = 0; j < 8; j++) mx = fmaxf(mx, sS[r][lane + 32 * j]);
        #pragma unroll
        for (int o = 16; o; o >>= 1) mx = fmaxf(mx, __shfl_xor_sync(0xffffffffu, mx, o));
        float sum = 0.f;
        #pragma unroll
        for (int j = 0; j < 8; j++) { e[j] = expf(sS[r][lane + 32 * j] - mx); sum += e[j]; }
        #pragma unroll
        for (int o = 16; o; o >>= 1) sum += __shfl_xor_sync(0xffffffffu, sum, o);
        float inv = 1.0f / sum;
        #pragma unroll
        for (int j = 0; j < 8; j++) sS[r][lane + 32 * j] = e[j] * inv;
    }
    __syncwarp();

    float o00 = 0, o01 = 0, o10 = 0, o11 = 0;
    for (int s = 0; s < 256; s++) {
        float p0 = sS[r0][s], p1 = sS[r1][s];
        const float* vr = Vb + (size_t)s * KVE;
        float v0 = vr[lane], v1 = vr[lane + 32];
        o00 += p0 * v0; o01 += p0 * v1;
        o10 += p1 * v0; o11 += p1 * v1;
    }
    float* Ob = g_att + ((size_t)(b * N_ + ntile * 16)) * D_ + qh * HD;
    Ob[(size_t)r0 * D_ + lane]      = o00;
    Ob[(size_t)r0 * D_ + lane + 32] = o01;
    Ob[(size_t)r1 * D_ + lane]      = o10;
    Ob[(size_t)r1 * D_ + lane + 32] = o11;
}

// ---------------- launch ----------------------------------------------------
extern "C" void kernel_launch(void* const* d_in, const int* in_sizes, int n_in,
                              void* d_out, int out_size) {
    const float* x  = (const float*)d_in[0];
    const float* y  = (const float*)d_in[1];
    const float* wq = (const float*)d_in[2];
    const float* wk = (const float*)d_in[3];
    const float* wv = (const float*)d_in[4];
    const float* wv_ = wv;
    const float* wo = (const float*)d_in[5];
    const float* gamma = (const float*)d_in[6];
    const float* beta  = (const float*)d_in[7];
    float* out = (float*)d_out;

    absmean_kernel<<<256, 256>>>(wq, D_ * D_, 0);
    absmean_kernel<<<256, 256>>>(wk, KVE * D_, 1);
    absmean_kernel<<<256, 256>>>(wv_, KVE * D_, 2);
    absmean_kernel<<<256, 256>>>(wo, D_ * D_, 3);
    reduce_kernel<<<4, 256>>>();
    wquant_kernel<<<512, 256>>>(wq, D_ * D_, 0, 1.0 / (1024.0 * 1024.0));
    wquant_kernel<<<256, 256>>>(wk, KVE * D_, 1, 1.0 / (512.0 * 1024.0));
    wquant_kernel<<<256, 256>>>(wv_, KVE * D_, 2, 1.0 / (512.0 * 1024.0));
    wquant_kernel<<<512, 256>>>(wo, D_ * D_, 3, 1.0 / (1024.0 * 1024.0));

    act_quant_kernel<<<B_ * N_, 256>>>(x, 0);
    act_quant_kernel<<<B_ * S_, 256>>>(y, 1);

    gemm_q_kernel<<<dim3(8, 128), 256>>>();
    gemm_k_kernel<<<dim3(4, 32), 256>>>();
    gemm_v_kernel<<<dim3(4, 32), 256>>>();

    attn_kernel<<<B_ * HQ * (N_ / 16), 256>>>();

    ln_quant_kernel<<<B_ * N_, 256>>>(gamma, beta);
    gemm_o_kernel<<<dim3(8, 128), 256>>>(out);
}

// round 3
// speedup vs baseline: 2.0172x; 2.0172x over previous
#include <cuda_runtime.h>
#include <cuda_bf16.h>
#include <cstdint>

#define B_  16
#define N_  1024
#define S_  256
#define D_  1024
#define HQ  16
#define HKV 8
#define HD  64
#define KVE 512

// ---------------- scratch (device globals; no cudaMalloc allowed) ----------
__device__ __nv_bfloat16 g_xq [(size_t)B_*N_*D_];
__device__ __nv_bfloat16 g_yq [(size_t)B_*S_*D_];
__device__ __nv_bfloat16 g_a2q[(size_t)B_*N_*D_];
__device__ __nv_bfloat16 g_wqt[D_*D_];
__device__ __nv_bfloat16 g_wkt[KVE*D_];
__device__ __nv_bfloat16 g_wvt[KVE*D_];
__device__ __nv_bfloat16 g_wot[D_*D_];
__device__ float  g_q  [(size_t)B_*N_*D_];
__device__ float  g_k  [(size_t)B_*S_*KVE];
__device__ float  g_v  [(size_t)B_*S_*KVE];
__device__ float  g_att[(size_t)B_*N_*D_];
__device__ float  g_rfx[B_*N_];
__device__ float  g_rfy[B_*S_];
__device__ float  g_rf2[B_*N_];
__device__ double g_part[4*256];
__device__ double g_wsum[4];

// ---------------- block reductions (256 threads) ----------------------------
__device__ __forceinline__ float block_sum(float v, float* sbuf) {
    #pragma unroll
    for (int o = 16; o; o >>= 1) v += __shfl_xor_sync(0xffffffffu, v, o);
    int w = threadIdx.x >> 5, l = threadIdx.x & 31;
    if (!l) sbuf[w] = v;
    __syncthreads();
    if (threadIdx.x < 8) {
        v = sbuf[threadIdx.x];
        #pragma unroll
        for (int o = 4; o; o >>= 1) v += __shfl_xor_sync(0x000000ffu, v, o);
        if (!threadIdx.x) sbuf[0] = v;
    }
    __syncthreads();
    v = sbuf[0];
    __syncthreads();
    return v;
}
__device__ __forceinline__ float block_max(float v, float* sbuf) {
    #pragma unroll
    for (int o = 16; o; o >>= 1) v = fmaxf(v, __shfl_xor_sync(0xffffffffu, v, o));
    int w = threadIdx.x >> 5, l = threadIdx.x & 31;
    if (!l) sbuf[w] = v;
    __syncthreads();
    if (threadIdx.x < 8) {
        v = sbuf[threadIdx.x];
        #pragma unroll
        for (int o = 4; o; o >>= 1) v = fmaxf(v, __shfl_xor_sync(0x000000ffu, v, o));
        if (!threadIdx.x) sbuf[0] = v;
    }
    __syncthreads();
    v = sbuf[0];
    __syncthreads();
    return v;
}

// ---------------- weight prep ----------------------------------------------
__global__ void __launch_bounds__(256) absmean_kernel(const float* __restrict__ w, int n, int slot) {
    __shared__ float sbuf[8];
    float s = 0.f;
    for (int i = blockIdx.x * 256 + threadIdx.x; i < n; i += 256 * 256)
        s += fabsf(w[i]);
    s = block_sum(s, sbuf);
    if (!threadIdx.x) g_part[slot * 256 + blockIdx.x] = (double)s;
}
__global__ void __launch_bounds__(256) reduce_kernel() {
    __shared__ double sd[256];
    int slot = blockIdx.x;
    sd[threadIdx.x] = g_part[slot * 256 + threadIdx.x];
    __syncthreads();
    for (int o = 128; o; o >>= 1) {
        if (threadIdx.x < o) sd[threadIdx.x] += sd[threadIdx.x + o];
        __syncthreads();
    }
    if (!threadIdx.x) g_wsum[slot] = sd[0];
}
__global__ void __launch_bounds__(256) wquant_kernel(const float* __restrict__ w, int n,
                                                     int slot, double invcnt) {
    __nv_bfloat16* out = slot == 0 ? g_wqt : slot == 1 ? g_wkt : slot == 2 ? g_wvt : g_wot;
    float mean  = (float)(g_wsum[slot] * invcnt);
    float scale = 1.0f / fmaxf(mean, 1e-5f);
    for (int i = blockIdx.x * 256 + threadIdx.x; i < n; i += gridDim.x * 256) {
        float t = fminf(fmaxf(rintf(w[i] * scale), -1.f), 1.f);
        out[i] = __float2bfloat16(t);
    }
}

// ---------------- activation quant: rms_norm + absmax int8 -----------------
__global__ void __launch_bounds__(256) act_quant_kernel(const float* __restrict__ X, int which) {
    __shared__ float sbuf[8];
    __nv_bfloat16* Q  = which ? g_yq : g_xq;
    float*         RF = which ? g_rfy : g_rfx;
    size_t row = blockIdx.x;
    int t = threadIdx.x;
    float4 xv = ((const float4*)(X + row * D_))[t];

    float ssq = xv.x*xv.x + xv.y*xv.y + xv.z*xv.z + xv.w*xv.w;
    ssq = block_sum(ssq, sbuf);
    float r = 1.0f / sqrtf(ssq * (1.0f/1024.0f) + 1e-6f);

    float am = fmaxf(fmaxf(fabsf(xv.x), fabsf(xv.y)), fmaxf(fabsf(xv.z), fabsf(xv.w)));
    am = block_max(am, sbuf) * r;
    float sc = 127.0f / fmaxf(am, 1e-5f);

    __nv_bfloat16* qr = Q + row * D_ + t * 4;
    qr[0] = __float2bfloat16(fminf(fmaxf(rintf((xv.x*r)*sc), -128.f), 127.f));
    qr[1] = __float2bfloat16(fminf(fmaxf(rintf((xv.y*r)*sc), -128.f), 127.f));
    qr[2] = __float2bfloat16(fminf(fmaxf(rintf((xv.z*r)*sc), -128.f), 127.f));
    qr[3] = __float2bfloat16(fminf(fmaxf(rintf((xv.w*r)*sc), -128.f), 127.f));
    if (!t) RF[row] = 1.0f / sc;
}

// ---------------- fused LayerNorm + rms_norm + act_quant -------------------
__global__ void __launch_bounds__(256) ln_quant_kernel(const float* __restrict__ gamma,
                                                       const float* __restrict__ beta) {
    __shared__ float sbuf[8];
    size_t row = blockIdx.x;
    int t = threadIdx.x;
    float4 xv = ((const float4*)(g_att + row * D_))[t];

    float mu = block_sum(xv.x + xv.y + xv.z + xv.w, sbuf) * (1.0f/1024.0f);
    float d0 = xv.x-mu, d1 = xv.y-mu, d2 = xv.z-mu, d3 = xv.w-mu;
    float var = block_sum(d0*d0 + d1*d1 + d2*d2 + d3*d3, sbuf) * (1.0f/1024.0f);
    float rs = 1.0f / sqrtf(var + 1e-5f);

    float4 gv = ((const float4*)gamma)[t];
    float4 bv = ((const float4*)beta)[t];
    float y0 = (d0*rs)*gv.x + bv.x, y1 = (d1*rs)*gv.y + bv.y;
    float y2 = (d2*rs)*gv.z + bv.z, y3 = (d3*rs)*gv.w + bv.w;

    float m2 = block_sum(y0*y0 + y1*y1 + y2*y2 + y3*y3, sbuf) * (1.0f/1024.0f);
    float r2 = 1.0f / sqrtf(m2 + 1e-6f);

    float am = fmaxf(fmaxf(fabsf(y0), fabsf(y1)), fmaxf(fabsf(y2), fabsf(y3)));
    am = block_max(am, sbuf) * r2;
    float sc = 127.0f / fmaxf(am, 1e-5f);

    __nv_bfloat16* qr = g_a2q + row * D_ + t * 4;
    qr[0] = __float2bfloat16(fminf(fmaxf(rintf((y0*r2)*sc), -128.f), 127.f));
    qr[1] = __float2bfloat16(fminf(fmaxf(rintf((y1*r2)*sc), -128.f), 127.f));
    qr[2] = __float2bfloat16(fminf(fmaxf(rintf((y2*r2)*sc), -128.f), 127.f));
    qr[3] = __float2bfloat16(fminf(fmaxf(rintf((y3*r2)*sc), -128.f), 127.f));
    if (!t) g_rf2[row] = 1.0f / sc;
}

// ---------------- mma / ldmatrix helpers ------------------------------------
__device__ __forceinline__ void ldsm4(uint32_t (&r)[4], uint32_t a) {
    asm volatile("ldmatrix.sync.aligned.m8n8.x4.shared.b16 {%0,%1,%2,%3}, [%4];"
                 : "=r"(r[0]), "=r"(r[1]), "=r"(r[2]), "=r"(r[3]) : "r"(a));
}
__device__ __forceinline__ void ldsm4t(uint32_t (&r)[4], uint32_t a) {
    asm volatile("ldmatrix.sync.aligned.m8n8.x4.trans.shared.b16 {%0,%1,%2,%3}, [%4];"
                 : "=r"(r[0]), "=r"(r[1]), "=r"(r[2]), "=r"(r[3]) : "r"(a));
}
__device__ __forceinline__ void mma_bf16(float (&d)[4], const uint32_t (&a)[4],
                                         uint32_t b0, uint32_t b1) {
    asm volatile("mma.sync.aligned.m16n8k16.row.col.f32.bf16.bf16.f32 "
                 "{%0,%1,%2,%3}, {%4,%5,%6,%7}, {%8,%9}, {%0,%1,%2,%3};"
                 : "+f"(d[0]), "+f"(d[1]), "+f"(d[2]), "+f"(d[3])
                 : "r"(a[0]), "r"(a[1]), "r"(a[2]), "r"(a[3]), "r"(b0), "r"(b1));
}
__device__ __forceinline__ void cpa16(uint32_t s, const void* g) {
    asm volatile("cp.async.cg.shared.global [%0], [%1], 16;" :: "r"(s), "l"(g));
}
#define CP_COMMIT asm volatile("cp.async.commit_group;")
#define CP_WAIT1  asm volatile("cp.async.wait_group 1;")
#define CP_WAIT0  asm volatile("cp.async.wait_group 0;")

// ---------------- exact integer GEMM via bf16 MMA (cp.async 2-stage) -------
__device__ __forceinline__ void gemm_core(const __nv_bfloat16* __restrict__ A,
                                          const __nv_bfloat16* __restrict__ W,
                                          float* __restrict__ C,
                                          const float* __restrict__ rowf,
                                          int slot, double invcnt,
                                          float extra, int Nn, int K) {
    __shared__ __align__(16) __nv_bfloat16 sA[2][128 * 40];
    __shared__ __align__(16) __nv_bfloat16 sB[2][128 * 40];
    int tid = threadIdx.x;
    int lane = tid & 31, w = tid >> 5;
    int warpM = w & 1, warpN = w >> 1;            // 2 x 4 warps -> 64x32 per warp
    int m0 = blockIdx.y * 128, n0 = blockIdx.x * 128;

    float acc[4][4][4];
    #pragma unroll
    for (int a = 0; a < 4; a++)
        #pragma unroll
        for (int b = 0; b < 4; b++)
            #pragma unroll
            for (int c = 0; c < 4; c++) acc[a][b][c] = 0.f;

    uint32_t sAb = (uint32_t)__cvta_generic_to_shared(&sA[0][0]);
    uint32_t sBb = (uint32_t)__cvta_generic_to_shared(&sB[0][0]);
    const uint32_t BUF = 128 * 40 * 2;            // bytes per stage
    int aRow = warpM * 64 + (lane & 15);
    int aCol = (lane >> 4) << 3;
    int bRow = warpN * 32 + ((lane & 16) >> 1) + (lane & 7);
    int bCol = lane & 8;

    int ldr = tid >> 2, ldsg = (tid & 3) * 8;     // 256 thr: each 2 rows per matrix

    // prologue: stage 0
    #pragma unroll
    for (int i = 0; i < 2; i++) {
        int r = ldr + i * 64;
        cpa16(sAb + (uint32_t)((r * 40 + ldsg) * 2), A + (size_t)(m0 + r) * K + ldsg);
        cpa16(sBb + (uint32_t)((r * 40 + ldsg) * 2), W + (size_t)(n0 + r) * K + ldsg);
    }
    CP_COMMIT;

    int T = K / 32;
    for (int t = 0; t < T; t++) {
        if (t + 1 < T) {
            uint32_t bo = ((t + 1) & 1) * BUF;
            int k0 = (t + 1) * 32;
            #pragma unroll
            for (int i = 0; i < 2; i++) {
                int r = ldr + i * 64;
                cpa16(sAb + bo + (uint32_t)((r * 40 + ldsg) * 2),
                      A + (size_t)(m0 + r) * K + k0 + ldsg);
                cpa16(sBb + bo + (uint32_t)((r * 40 + ldsg) * 2),
                      W + (size_t)(n0 + r) * K + k0 + ldsg);
            }
            CP_COMMIT;
            CP_WAIT1;
        } else {
            CP_WAIT0;
        }
        __syncthreads();
        uint32_t bo = (t & 1) * BUF;
        #pragma unroll
        for (int ks = 0; ks < 32; ks += 16) {
            uint32_t af[4][4];
            #pragma unroll
            for (int mi = 0; mi < 4; mi++)
                ldsm4(af[mi], sAb + bo + (uint32_t)(((aRow + mi * 16) * 40 + ks + aCol) * 2));
            uint32_t bf[2][4];
            #pragma unroll
            for (int nb = 0; nb < 2; nb++)
                ldsm4(bf[nb], sBb + bo + (uint32_t)(((bRow + nb * 16) * 40 + ks + bCol) * 2));
            #pragma unroll
            for (int mi = 0; mi < 4; mi++)
                #pragma unroll
                for (int ni = 0; ni < 4; ni++)
                    mma_bf16(acc[mi][ni], af[mi],
                             bf[ni >> 1][(ni & 1) * 2], bf[ni >> 1][(ni & 1) * 2 + 1]);
        }
        __syncthreads();
    }

    float wf = fmaxf((float)(g_wsum[slot] * invcnt), 1e-5f);
    float sgl = wf * extra;
    #pragma unroll
    for (int mi = 0; mi < 4; mi++) {
        int m = m0 + warpM * 64 + mi * 16 + (lane >> 2);
        float f0 = rowf[m] * sgl, f1 = rowf[m + 8] * sgl;
        #pragma unroll
        for (int ni = 0; ni < 4; ni++) {
            int n = n0 + warpN * 32 + ni * 8 + (lane & 3) * 2;
            *(float2*)(C + (size_t)m * Nn + n) =
                make_float2(acc[mi][ni][0] * f0, acc[mi][ni][1] * f0);
            *(float2*)(C + (size_t)(m + 8) * Nn + n) =
                make_float2(acc[mi][ni][2] * f1, acc[mi][ni][3] * f1);
        }
    }
}

__global__ void __launch_bounds__(256) gemm_q_kernel() {
    gemm_core(g_xq, g_wqt, g_q, g_rfx, 0, 1.0/(1024.0*1024.0), 0.125f, D_, D_);
}
__global__ void __launch_bounds__(256) gemm_k_kernel() {
    gemm_core(g_yq, g_wkt, g_k, g_rfy, 1, 1.0/(512.0*1024.0), 1.0f, KVE, D_);
}
__global__ void __launch_bounds__(256) gemm_v_kernel() {
    gemm_core(g_yq, g_wvt, g_v, g_rfy, 2, 1.0/(512.0*1024.0), 1.0f, KVE, D_);
}
__global__ void __launch_bounds__(256) gemm_o_kernel(float* __restrict__ out) {
    gemm_core(g_a2q, g_wot, out, g_rf2, 3, 1.0/(1024.0*1024.0), 1.0f, D_, D_);
}

// ---------------- attention: hi/lo-split bf16 MMA (fp32-accurate) ----------
__device__ __forceinline__ void split_store(float v, __nv_bfloat16* hi, __nv_bfloat16* lo) {
    __nv_bfloat16 h = __float2bfloat16(v);
    *hi = h;
    *lo = __float2bfloat16(v - __bfloat162float(h));
}
__device__ __forceinline__ uint32_t pack_hl(float x, float y, uint32_t& lo) {
    __nv_bfloat16 hx = __float2bfloat16(x), hy = __float2bfloat16(y);
    __nv_bfloat16 lx = __float2bfloat16(x - __bfloat162float(hx));
    __nv_bfloat16 ly = __float2bfloat16(y - __bfloat162float(hy));
    lo = ((uint32_t)__bfloat16_as_ushort(ly) << 16) | __bfloat16_as_ushort(lx);
    return ((uint32_t)__bfloat16_as_ushort(hy) << 16) | __bfloat16_as_ushort(hx);
}

#define ATT_SMEM ((2 * 256 * 72 + 2 * 64 * 72) * 2)

__global__ void __launch_bounds__(128) attn_mma_kernel() {
    extern __shared__ __nv_bfloat16 sm[];
    __nv_bfloat16* sKVh = sm;                    // [256][72] K, later V (hi)
    __nv_bfloat16* sKVl = sm + 256 * 72;         // (lo)
    __nv_bfloat16* sQh  = sm + 2 * 256 * 72;     // [64][72]
    __nv_bfloat16* sQl  = sQh + 64 * 72;

    int tid = threadIdx.x, lane = tid & 31, w = tid >> 5;
    int blk = blockIdx.x;
    int qt = blk & 15, qh = (blk >> 4) & 15, b = blk >> 8;
    int h = qh >> 1;

    const float* Qg = g_q + ((size_t)(b * N_ + qt * 64)) * D_ + qh * HD;
    const float* Kg = g_k + (size_t)b * S_ * KVE + h * HD;
    const float* Vg = g_v + (size_t)b * S_ * KVE + h * HD;

    for (int i = tid; i < 64 * 16; i += 128) {
        int r = i >> 4, c = (i & 15) * 4;
        float4 v = *(const float4*)(Qg + (size_t)r * D_ + c);
        split_store(v.x, &sQh[r*72+c  ], &sQl[r*72+c  ]);
        split_store(v.y, &sQh[r*72+c+1], &sQl[r*72+c+1]);
        split_store(v.z, &sQh[r*72+c+2], &sQl[r*72+c+2]);
        split_store(v.w, &sQh[r*72+c+3], &sQl[r*72+c+3]);
    }
    for (int i = tid; i < 256 * 16; i += 128) {
        int r = i >> 4, c = (i & 15) * 4;
        float4 v = *(const float4*)(Kg + (size_t)r * KVE + c);
        split_store(v.x, &sKVh[r*72+c  ], &sKVl[r*72+c  ]);
        split_store(v.y, &sKVh[r*72+c+1], &sKVl[r*72+c+1]);
        split_store(v.z, &sKVh[r*72+c+2], &sKVl[r*72+c+2]);
        split_store(v.w, &sKVh[r*72+c+3], &sKVl[r*72+c+3]);
    }
    __syncthreads();

    uint32_t sQhB  = (uint32_t)__cvta_generic_to_shared(sQh);
    uint32_t sQlB  = (uint32_t)__cvta_generic_to_shared(sQl);
    uint32_t sKVhB = (uint32_t)__cvta_generic_to_shared(sKVh);
    uint32_t sKVlB = (uint32_t)__cvta_generic_to_shared(sKVl);

    // Q fragments (A operand, M16 per warp, K=64 -> 4 k-tiles)
    int arow = w * 16 + (lane & 15);
    int acb  = (lane & 16) >> 1;
    uint32_t qhf[4][4], qlf[4][4];
    #pragma unroll
    for (int kt = 0; kt < 4; kt++) {
        uint32_t off = (uint32_t)((arow * 72 + kt * 16 + acb) * 2);
        ldsm4(qhf[kt], sQhB + off);
        ldsm4(qlf[kt], sQlB + off);
    }

    // scores: c[32 n-tiles][4] fp32 in registers
    float c[32][4];
    #pragma unroll
    for (int i = 0; i < 32; i++)
        #pragma unroll
        for (int j = 0; j < 4; j++) c[i][j] = 0.f;

    int brow = (lane & 7) + ((lane & 16) >> 1);
    int bcol = lane & 8;
    #pragma unroll
    for (int np = 0; np < 16; np++) {
        #pragma unroll
        for (int kt = 0; kt < 4; kt++) {
            uint32_t off = (uint32_t)(((np * 16 + brow) * 72 + kt * 16 + bcol) * 2);
            uint32_t bh[4], bl[4];
            ldsm4(bh, sKVhB + off);
            ldsm4(bl, sKVlB + off);
            mma_bf16(c[2*np  ], qhf[kt], bh[0], bh[1]);
            mma_bf16(c[2*np  ], qhf[kt], bl[0], bl[1]);
            mma_bf16(c[2*np  ], qlf[kt], bh[0], bh[1]);
            mma_bf16(c[2*np+1], qhf[kt], bh[2], bh[3]);
            mma_bf16(c[2*np+1], qhf[kt], bl[2], bl[3]);
            mma_bf16(c[2*np+1], qlf[kt], bh[2], bh[3]);
        }
    }
    __syncthreads();   // done reading K

    // overwrite K buffer with V
    for (int i = tid; i < 256 * 16; i += 128) {
        int r = i >> 4, cc = (i & 15) * 4;
        float4 v = *(const float4*)(Vg + (size_t)r * KVE + cc);
        split_store(v.x, &sKVh[r*72+cc  ], &sKVl[r*72+cc  ]);
        split_store(v.y, &sKVh[r*72+cc+1], &sKVl[r*72+cc+1]);
        split_store(v.z, &sKVh[r*72+cc+2], &sKVl[r*72+cc+2]);
        split_store(v.w, &sKVh[r*72+cc+3], &sKVl[r*72+cc+3]);
    }

    // register softmax: row r0 = lane>>2 holds c[*][0..1], row r0+8 holds c[*][2..3]
    float mx0 = -1e30f, mx1 = -1e30f;
    #pragma unroll
    for (int nt = 0; nt < 32; nt++) {
        mx0 = fmaxf(mx0, fmaxf(c[nt][0], c[nt][1]));
        mx1 = fmaxf(mx1, fmaxf(c[nt][2], c[nt][3]));
    }
    mx0 = fmaxf(mx0, __shfl_xor_sync(0xffffffffu, mx0, 1));
    mx0 = fmaxf(mx0, __shfl_xor_sync(0xffffffffu, mx0, 2));
    mx1 = fmaxf(mx1, __shfl_xor_sync(0xffffffffu, mx1, 1));
    mx1 = fmaxf(mx1, __shfl_xor_sync(0xffffffffu, mx1, 2));
    float s0 = 0.f, s1 = 0.f;
    #pragma unroll
    for (int nt = 0; nt < 32; nt++) {
        c[nt][0] = __expf(c[nt][0] - mx0); s0 += c[nt][0];
        c[nt][1] = __expf(c[nt][1] - mx0); s0 += c[nt][1];
        c[nt][2] = __expf(c[nt][2] - mx1); s1 += c[nt][2];
        c[nt][3] = __expf(c[nt][3] - mx1); s1 += c[nt][3];
    }
    s0 += __shfl_xor_sync(0xffffffffu, s0, 1);
    s0 += __shfl_xor_sync(0xffffffffu, s0, 2);
    s1 += __shfl_xor_sync(0xffffffffu, s1, 1);
    s1 += __shfl_xor_sync(0xffffffffu, s1, 2);
    float i0 = 1.0f / s0, i1 = 1.0f / s1;
    #pragma unroll
    for (int nt = 0; nt < 32; nt++) {
        c[nt][0] *= i0; c[nt][1] *= i0; c[nt][2] *= i1; c[nt][3] *= i1;
    }
    __syncthreads();   // V ready

    // PV: out[16 x 64] per warp, K(=s)=256 in 16 chunks, B = V^T via ldmatrix.trans
    float o[8][4];
    #pragma unroll
    for (int i = 0; i < 8; i++)
        #pragma unroll
        for (int j = 0; j < 4; j++) o[i][j] = 0.f;

    int vrow = (lane & 7) + (lane & 8);
    int vcb  = (lane & 16) >> 1;
    #pragma unroll
    for (int kt = 0; kt < 16; kt++) {
        uint32_t phi[4], plo[4];
        phi[0] = pack_hl(c[2*kt  ][0], c[2*kt  ][1], plo[0]);
        phi[1] = pack_hl(c[2*kt  ][2], c[2*kt  ][3], plo[1]);
        phi[2] = pack_hl(c[2*kt+1][0], c[2*kt+1][1], plo[2]);
        phi[3] = pack_hl(c[2*kt+1][2], c[2*kt+1][3], plo[3]);
        #pragma unroll
        for (int dp = 0; dp < 4; dp++) {
            uint32_t off = (uint32_t)(((kt * 16 + vrow) * 72 + dp * 16 + vcb) * 2);
            uint32_t bh[4], bl[4];
            ldsm4t(bh, sKVhB + off);
            ldsm4t(bl, sKVlB + off);
            mma_bf16(o[2*dp  ], phi, bh[0], bh[1]);
            mma_bf16(o[2*dp  ], phi, bl[0], bl[1]);
            mma_bf16(o[2*dp  ], plo, bh[0], bh[1]);
            mma_bf16(o[2*dp+1], phi, bh[2], bh[3]);
            mma_bf16(o[2*dp+1], phi, bl[2], bl[3]);
            mma_bf16(o[2*dp+1], plo, bh[2], bh[3]);
        }
    }

    float* Ob = g_att + ((size_t)(b * N_ + qt * 64 + w * 16 + (lane >> 2))) * D_ + qh * HD;
    #pragma unroll
    for (int nt = 0; nt < 8; nt++) {
        int col = nt * 8 + (lane & 3) * 2;
        *(float2*)(Ob + col)          = make_float2(o[nt][0], o[nt][1]);
        *(float2*)(Ob + 8 * D_ + col) = make_float2(o[nt][2], o[nt][3]);
    }
}

// ---------------- launch ----------------------------------------------------
extern "C" void kernel_launch(void* const* d_in, const int* in_sizes, int n_in,
                              void* d_out, int out_size) {
    const float* x  = (const float*)d_in[0];
    const float* y  = (const float*)d_in[1];
    const float* wq = (const float*)d_in[2];
    const float* wk = (const float*)d_in[3];
    const float* wv = (const float*)d_in[4];
    const float* wo = (const float*)d_in[5];
    const float* gamma = (const float*)d_in[6];
    const float* beta  = (const float*)d_in[7];
    float* out = (float*)d_out;

    cudaFuncSetAttribute(attn_mma_kernel,
                         cudaFuncAttributeMaxDynamicSharedMemorySize, ATT_SMEM);

    absmean_kernel<<<256, 256>>>(wq, D_ * D_, 0);
    absmean_kernel<<<256, 256>>>(wk, KVE * D_, 1);
    absmean_kernel<<<256, 256>>>(wv, KVE * D_, 2);
    absmean_kernel<<<256, 256>>>(wo, D_ * D_, 3);
    reduce_kernel<<<4, 256>>>();
    wquant_kernel<<<512, 256>>>(wq, D_ * D_, 0, 1.0 / (1024.0 * 1024.0));
    wquant_kernel<<<256, 256>>>(wk, KVE * D_, 1, 1.0 / (512.0 * 1024.0));
    wquant_kernel<<<256, 256>>>(wv, KVE * D_, 2, 1.0 / (512.0 * 1024.0));
    wquant_kernel<<<512, 256>>>(wo, D_ * D_, 3, 1.0 / (1024.0 * 1024.0));

    act_quant_kernel<<<B_ * N_, 256>>>(x, 0);
    act_quant_kernel<<<B_ * S_, 256>>>(y, 1);

    gemm_q_kernel<<<dim3(8, 128), 256>>>();
    gemm_k_kernel<<<dim3(4, 32), 256>>>();
    gemm_v_kernel<<<dim3(4, 32), 256>>>();

    attn_mma_kernel<<<B_ * HQ * (N_ / 64), 128, ATT_SMEM>>>();

    ln_quant_kernel<<<B_ * N_, 256>>>(gamma, beta);
    gemm_o_kernel<<<dim3(8, 128), 256>>>(out);
}

// round 5
// speedup vs baseline: 2.5915x; 1.2847x over previous
#include <cuda_runtime.h>
#include <cuda_bf16.h>
#include <cstdint>

#define B_  16
#define N_  1024
#define S_  256
#define D_  1024
#define HQ  16
#define HKV 8
#define HD  64
#define KVE 512

// ---------------- scratch (device globals; no cudaMalloc allowed) ----------
__device__ __nv_bfloat16 g_xq [(size_t)B_*N_*D_];
__device__ __nv_bfloat16 g_yq [(size_t)B_*S_*D_];
__device__ __nv_bfloat16 g_a2q[(size_t)B_*N_*D_];
__device__ __nv_bfloat16 g_wqt[D_*D_];
__device__ __nv_bfloat16 g_wkt[KVE*D_];
__device__ __nv_bfloat16 g_wvt[KVE*D_];
__device__ __nv_bfloat16 g_wot[D_*D_];
// hi/lo bf16 planes for q/k/v (exact fp32 split)
__device__ __nv_bfloat16 g_qh[(size_t)B_*N_*D_];
__device__ __nv_bfloat16 g_ql[(size_t)B_*N_*D_];
__device__ __nv_bfloat16 g_kh[(size_t)B_*S_*KVE];
__device__ __nv_bfloat16 g_kl[(size_t)B_*S_*KVE];
__device__ __nv_bfloat16 g_vh[(size_t)B_*S_*KVE];
__device__ __nv_bfloat16 g_vl[(size_t)B_*S_*KVE];
__device__ float  g_att[(size_t)B_*N_*D_];
__device__ float  g_rfx[B_*N_];
__device__ float  g_rfy[B_*S_];
__device__ float  g_rf2[B_*N_];
__device__ double g_part[4*256];
__device__ double g_wsum[4];

// ---------------- block reductions (256 threads) ----------------------------
__device__ __forceinline__ float block_sum(float v, float* sbuf) {
    #pragma unroll
    for (int o = 16; o; o >>= 1) v += __shfl_xor_sync(0xffffffffu, v, o);
    int w = threadIdx.x >> 5, l = threadIdx.x & 31;
    if (!l) sbuf[w] = v;
    __syncthreads();
    if (threadIdx.x < 8) {
        v = sbuf[threadIdx.x];
        #pragma unroll
        for (int o = 4; o; o >>= 1) v += __shfl_xor_sync(0x000000ffu, v, o);
        if (!threadIdx.x) sbuf[0] = v;
    }
    __syncthreads();
    v = sbuf[0];
    __syncthreads();
    return v;
}
__device__ __forceinline__ float block_max(float v, float* sbuf) {
    #pragma unroll
    for (int o = 16; o; o >>= 1) v = fmaxf(v, __shfl_xor_sync(0xffffffffu, v, o));
    int w = threadIdx.x >> 5, l = threadIdx.x & 31;
    if (!l) sbuf[w] = v;
    __syncthreads();
    if (threadIdx.x < 8) {
        v = sbuf[threadIdx.x];
        #pragma unroll
        for (int o = 4; o; o >>= 1) v = fmaxf(v, __shfl_xor_sync(0x000000ffu, v, o));
        if (!threadIdx.x) sbuf[0] = v;
    }
    __syncthreads();
    v = sbuf[0];
    __syncthreads();
    return v;
}

// ---------------- weight prep (fused) ----------------------------------------
__global__ void __launch_bounds__(256) absmean_all_kernel(const float* __restrict__ w0,
    const float* __restrict__ w1, const float* __restrict__ w2, const float* __restrict__ w3) {
    __shared__ float sbuf[8];
    int slot = blockIdx.y;
    const float* w = slot == 0 ? w0 : slot == 1 ? w1 : slot == 2 ? w2 : w3;
    int n = (slot == 1 || slot == 2) ? KVE * D_ : D_ * D_;
    float s = 0.f;
    for (int i = blockIdx.x * 256 + threadIdx.x; i < n; i += 256 * 256)
        s += fabsf(w[i]);
    s = block_sum(s, sbuf);
    if (!threadIdx.x) g_part[slot * 256 + blockIdx.x] = (double)s;
}
__global__ void __launch_bounds__(256) reduce_kernel() {
    __shared__ double sd[256];
    int slot = blockIdx.x;
    sd[threadIdx.x] = g_part[slot * 256 + threadIdx.x];
    __syncthreads();
    for (int o = 128; o; o >>= 1) {
        if (threadIdx.x < o) sd[threadIdx.x] += sd[threadIdx.x + o];
        __syncthreads();
    }
    if (!threadIdx.x) g_wsum[slot] = sd[0];
}
__global__ void __launch_bounds__(256) wquant_all_kernel(const float* __restrict__ w0,
    const float* __restrict__ w1, const float* __restrict__ w2, const float* __restrict__ w3) {
    int slot = blockIdx.y;
    const float* w = slot == 0 ? w0 : slot == 1 ? w1 : slot == 2 ? w2 : w3;
    __nv_bfloat16* out = slot == 0 ? g_wqt : slot == 1 ? g_wkt : slot == 2 ? g_wvt : g_wot;
    int n = (slot == 1 || slot == 2) ? KVE * D_ : D_ * D_;
    double invcnt = 1.0 / (double)n;
    float mean  = (float)(g_wsum[slot] * invcnt);
    float scale = 1.0f / fmaxf(mean, 1e-5f);
    for (int i = blockIdx.x * 256 + threadIdx.x; i < n; i += gridDim.x * 256) {
        float t = fminf(fmaxf(rintf(w[i] * scale), -1.f), 1.f);
        out[i] = __float2bfloat16(t);
    }
}

// ---------------- activation quant (x and y fused) ---------------------------
__global__ void __launch_bounds__(256) act_quant_kernel(const float* __restrict__ X,
                                                        const float* __restrict__ Y) {
    __shared__ float sbuf[8];
    int which = blockIdx.x >= B_ * N_;
    size_t row = which ? blockIdx.x - B_ * N_ : blockIdx.x;
    const float* src = which ? Y : X;
    __nv_bfloat16* Q  = which ? g_yq : g_xq;
    float*         RF = which ? g_rfy : g_rfx;
    int t = threadIdx.x;
    float4 xv = ((const float4*)(src + row * D_))[t];

    float ssq = xv.x*xv.x + xv.y*xv.y + xv.z*xv.z + xv.w*xv.w;
    ssq = block_sum(ssq, sbuf);
    float r = 1.0f / sqrtf(ssq * (1.0f/1024.0f) + 1e-6f);

    float am = fmaxf(fmaxf(fabsf(xv.x), fabsf(xv.y)), fmaxf(fabsf(xv.z), fabsf(xv.w)));
    am = block_max(am, sbuf) * r;
    float sc = 127.0f / fmaxf(am, 1e-5f);

    __nv_bfloat16* qr = Q + row * D_ + t * 4;
    qr[0] = __float2bfloat16(fminf(fmaxf(rintf((xv.x*r)*sc), -128.f), 127.f));
    qr[1] = __float2bfloat16(fminf(fmaxf(rintf((xv.y*r)*sc), -128.f), 127.f));
    qr[2] = __float2bfloat16(fminf(fmaxf(rintf((xv.z*r)*sc), -128.f), 127.f));
    qr[3] = __float2bfloat16(fminf(fmaxf(rintf((xv.w*r)*sc), -128.f), 127.f));
    if (!t) RF[row] = 1.0f / sc;
}

// ---------------- fused LayerNorm + rms_norm + act_quant -------------------
__global__ void __launch_bounds__(256) ln_quant_kernel(const float* __restrict__ gamma,
                                                       const float* __restrict__ beta) {
    __shared__ float sbuf[8];
    size_t row = blockIdx.x;
    int t = threadIdx.x;
    float4 xv = ((const float4*)(g_att + row * D_))[t];

    float mu = block_sum(xv.x + xv.y + xv.z + xv.w, sbuf) * (1.0f/1024.0f);
    float d0 = xv.x-mu, d1 = xv.y-mu, d2 = xv.z-mu, d3 = xv.w-mu;
    float var = block_sum(d0*d0 + d1*d1 + d2*d2 + d3*d3, sbuf) * (1.0f/1024.0f);
    float rs = 1.0f / sqrtf(var + 1e-5f);

    float4 gv = ((const float4*)gamma)[t];
    float4 bv = ((const float4*)beta)[t];
    float y0 = (d0*rs)*gv.x + bv.x, y1 = (d1*rs)*gv.y + bv.y;
    float y2 = (d2*rs)*gv.z + bv.z, y3 = (d3*rs)*gv.w + bv.w;

    float m2 = block_sum(y0*y0 + y1*y1 + y2*y2 + y3*y3, sbuf) * (1.0f/1024.0f);
    float r2 = 1.0f / sqrtf(m2 + 1e-6f);

    float am = fmaxf(fmaxf(fabsf(y0), fabsf(y1)), fmaxf(fabsf(y2), fabsf(y3)));
    am = block_max(am, sbuf) * r2;
    float sc = 127.0f / fmaxf(am, 1e-5f);

    __nv_bfloat16* qr = g_a2q + row * D_ + t * 4;
    qr[0] = __float2bfloat16(fminf(fmaxf(rintf((y0*r2)*sc), -128.f), 127.f));
    qr[1] = __float2bfloat16(fminf(fmaxf(rintf((y1*r2)*sc), -128.f), 127.f));
    qr[2] = __float2bfloat16(fminf(fmaxf(rintf((y2*r2)*sc), -128.f), 127.f));
    qr[3] = __float2bfloat16(fminf(fmaxf(rintf((y3*r2)*sc), -128.f), 127.f));
    if (!t) g_rf2[row] = 1.0f / sc;
}

// ---------------- mma / ldmatrix / cp.async helpers -------------------------
__device__ __forceinline__ void ldsm4(uint32_t (&r)[4], uint32_t a) {
    asm volatile("ldmatrix.sync.aligned.m8n8.x4.shared.b16 {%0,%1,%2,%3}, [%4];"
                 : "=r"(r[0]), "=r"(r[1]), "=r"(r[2]), "=r"(r[3]) : "r"(a));
}
__device__ __forceinline__ void ldsm4t(uint32_t (&r)[4], uint32_t a) {
    asm volatile("ldmatrix.sync.aligned.m8n8.x4.trans.shared.b16 {%0,%1,%2,%3}, [%4];"
                 : "=r"(r[0]), "=r"(r[1]), "=r"(r[2]), "=r"(r[3]) : "r"(a));
}
__device__ __forceinline__ void mma_bf16(float (&d)[4], const uint32_t (&a)[4],
                                         uint32_t b0, uint32_t b1) {
    asm volatile("mma.sync.aligned.m16n8k16.row.col.f32.bf16.bf16.f32 "
                 "{%0,%1,%2,%3}, {%4,%5,%6,%7}, {%8,%9}, {%0,%1,%2,%3};"
                 : "+f"(d[0]), "+f"(d[1]), "+f"(d[2]), "+f"(d[3])
                 : "r"(a[0]), "r"(a[1]), "r"(a[2]), "r"(a[3]), "r"(b0), "r"(b1));
}
__device__ __forceinline__ void cpa16(uint32_t s, const void* g) {
    asm volatile("cp.async.cg.shared.global [%0], [%1], 16;" :: "r"(s), "l"(g));
}
#define CP_COMMIT asm volatile("cp.async.commit_group;")
#define CP_WAIT2  asm volatile("cp.async.wait_group 2;")
#define CP_WAIT0  asm volatile("cp.async.wait_group 0;")

__device__ __forceinline__ uint32_t pack_hl(float x, float y, uint32_t& lo) {
    __nv_bfloat16 hx = __float2bfloat16(x), hy = __float2bfloat16(y);
    __nv_bfloat16 lx = __float2bfloat16(x - __bfloat162float(hx));
    __nv_bfloat16 ly = __float2bfloat16(y - __bfloat162float(hy));
    lo = ((uint32_t)__bfloat16_as_ushort(ly) << 16) | __bfloat16_as_ushort(lx);
    return ((uint32_t)__bfloat16_as_ushort(hy) << 16) | __bfloat16_as_ushort(hx);
}

// ---------------- exact integer GEMM via bf16 MMA (4-stage cp.async) -------
// MODE 0: C fp32.  MODE 1: hi/lo bf16 planes.
#define G_SMEM4 (4 * 10240 * 2)
template<int MODE>
__device__ __forceinline__ void gemm4(const __nv_bfloat16* __restrict__ A,
                                      const __nv_bfloat16* __restrict__ W,
                                      float* __restrict__ C,
                                      __nv_bfloat16* __restrict__ Ch,
                                      __nv_bfloat16* __restrict__ Cl,
                                      const float* __restrict__ rowf,
                                      int slot, double invcnt, float extra, int Nn) {
    extern __shared__ char smg[];
    __nv_bfloat16* sA = (__nv_bfloat16*)smg;                 // 4 stages x 128x40
    __nv_bfloat16* sB = (__nv_bfloat16*)(smg + 4 * 10240);
    const int K = 1024, T = 32;
    int tid = threadIdx.x, lane = tid & 31, w = tid >> 5;
    int warpM = w & 1, warpN = w >> 1;            // 2 x 4 warps -> 64x32 per warp
    int m0 = blockIdx.y * 128, n0 = blockIdx.x * 128;

    float acc[4][4][4];
    #pragma unroll
    for (int a = 0; a < 4; a++)
        #pragma unroll
        for (int b = 0; b < 4; b++)
            #pragma unroll
            for (int c = 0; c < 4; c++) acc[a][b][c] = 0.f;

    uint32_t sAb = (uint32_t)__cvta_generic_to_shared(sA);
    uint32_t sBb = (uint32_t)__cvta_generic_to_shared(sB);
    int aRow = warpM * 64 + (lane & 15);
    int aCol = (lane >> 4) << 3;
    int bRow = warpN * 32 + ((lane & 16) >> 1) + (lane & 7);
    int bCol = lane & 8;
    int ldr = tid >> 2, ldsg = (tid & 3) * 8;

    #define GLOAD(t, buf) do {                                                 \
        uint32_t bo = (uint32_t)(buf) * 10240u;                                \
        int k0 = (t) * 32;                                                     \
        _Pragma("unroll")                                                      \
        for (int i = 0; i < 2; i++) {                                          \
            int r = ldr + i * 64;                                              \
            cpa16(sAb + bo + (uint32_t)((r * 40 + ldsg) * 2),                  \
                  A + (size_t)(m0 + r) * K + k0 + ldsg);                       \
            cpa16(sBb + bo + (uint32_t)((r * 40 + ldsg) * 2),                  \
                  W + (size_t)(n0 + r) * K + k0 + ldsg);                       \
        }                                                                      \
    } while (0)

    GLOAD(0, 0); CP_COMMIT;
    GLOAD(1, 1); CP_COMMIT;
    GLOAD(2, 2); CP_COMMIT;

    #pragma unroll 1
    for (int t = 0; t < T; t++) {
        CP_WAIT2;
        __syncthreads();
        if (t + 3 < T) GLOAD(t + 3, (t + 3) & 3);
        CP_COMMIT;
        uint32_t bo = (uint32_t)(t & 3) * 10240u;
        #pragma unroll
        for (int ks = 0; ks < 32; ks += 16) {
            uint32_t af[4][4];
            #pragma unroll
            for (int mi = 0; mi < 4; mi++)
                ldsm4(af[mi], sAb + bo + (uint32_t)(((aRow + mi * 16) * 40 + ks + aCol) * 2));
            uint32_t bf[2][4];
            #pragma unroll
            for (int nb = 0; nb < 2; nb++)
                ldsm4(bf[nb], sBb + bo + (uint32_t)(((bRow + nb * 16) * 40 + ks + bCol) * 2));
            #pragma unroll
            for (int mi = 0; mi < 4; mi++)
                #pragma unroll
                for (int ni = 0; ni < 4; ni++)
                    mma_bf16(acc[mi][ni], af[mi],
                             bf[ni >> 1][(ni & 1) * 2], bf[ni >> 1][(ni & 1) * 2 + 1]);
        }
        __syncthreads();
    }
    #undef GLOAD

    float wf = fmaxf((float)(g_wsum[slot] * invcnt), 1e-5f);
    float sgl = wf * extra;
    #pragma unroll
    for (int mi = 0; mi < 4; mi++) {
        int m = m0 + warpM * 64 + mi * 16 + (lane >> 2);
        float f0 = rowf[m] * sgl, f1 = rowf[m + 8] * sgl;
        #pragma unroll
        for (int ni = 0; ni < 4; ni++) {
            int n = n0 + warpN * 32 + ni * 8 + (lane & 3) * 2;
            if (MODE == 0) {
                *(float2*)(C + (size_t)m * Nn + n) =
                    make_float2(acc[mi][ni][0] * f0, acc[mi][ni][1] * f0);
                *(float2*)(C + (size_t)(m + 8) * Nn + n) =
                    make_float2(acc[mi][ni][2] * f1, acc[mi][ni][3] * f1);
            } else {
                uint32_t lo0, lo1;
                uint32_t hi0 = pack_hl(acc[mi][ni][0] * f0, acc[mi][ni][1] * f0, lo0);
                uint32_t hi1 = pack_hl(acc[mi][ni][2] * f1, acc[mi][ni][3] * f1, lo1);
                *(uint32_t*)(Ch + (size_t)m * Nn + n) = hi0;
                *(uint32_t*)(Cl + (size_t)m * Nn + n) = lo0;
                *(uint32_t*)(Ch + (size_t)(m + 8) * Nn + n) = hi1;
                *(uint32_t*)(Cl + (size_t)(m + 8) * Nn + n) = lo1;
            }
        }
    }
}

__global__ void __launch_bounds__(256) gemm_q_kernel() {
    gemm4<1>(g_xq, g_wqt, nullptr, g_qh, g_ql, g_rfx, 0, 1.0/(1024.0*1024.0), 0.125f, D_);
}
__global__ void __launch_bounds__(256) gemm_kv_kernel() {
    if (blockIdx.z == 0)
        gemm4<1>(g_yq, g_wkt, nullptr, g_kh, g_kl, g_rfy, 1, 1.0/(512.0*1024.0), 1.0f, KVE);
    else
        gemm4<1>(g_yq, g_wvt, nullptr, g_vh, g_vl, g_rfy, 2, 1.0/(512.0*1024.0), 1.0f, KVE);
}
__global__ void __launch_bounds__(256) gemm_o_kernel(float* __restrict__ out) {
    gemm4<0>(g_a2q, g_wot, out, nullptr, nullptr, g_rf2, 3, 1.0/(1024.0*1024.0), 1.0f, D_);
}

// ---------------- attention: hi/lo-split bf16 MMA (fp32-accurate) ----------
// smem: sKVh[256][72], sKVl[256][72], sQh[64][72], sQl[64][72]  (bf16)
#define ATT_SMEM ((2 * 256 * 72 + 2 * 64 * 72) * 2)

__global__ void __launch_bounds__(128) attn_mma_kernel() {
    extern __shared__ __nv_bfloat16 sm[];
    __nv_bfloat16* sKVh = sm;
    __nv_bfloat16* sKVl = sm + 256 * 72;
    __nv_bfloat16* sQh  = sm + 2 * 256 * 72;
    __nv_bfloat16* sQl  = sQh + 64 * 72;

    int tid = threadIdx.x, lane = tid & 31, w = tid >> 5;
    int blk = blockIdx.x;
    int qt = blk & 15, qh = (blk >> 4) & 15, b = blk >> 8;
    int h = qh >> 1;

    uint32_t sQhB  = (uint32_t)__cvta_generic_to_shared(sQh);
    uint32_t sQlB  = (uint32_t)__cvta_generic_to_shared(sQl);
    uint32_t sKVhB = (uint32_t)__cvta_generic_to_shared(sKVh);
    uint32_t sKVlB = (uint32_t)__cvta_generic_to_shared(sKVl);

    const __nv_bfloat16* Qh = g_qh + ((size_t)(b * N_ + qt * 64)) * D_ + qh * HD;
    const __nv_bfloat16* Ql = g_ql + ((size_t)(b * N_ + qt * 64)) * D_ + qh * HD;
    const __nv_bfloat16* Kh = g_kh + (size_t)b * S_ * KVE + h * HD;
    const __nv_bfloat16* Kl = g_kl + (size_t)b * S_ * KVE + h * HD;
    const __nv_bfloat16* Vh = g_vh + (size_t)b * S_ * KVE + h * HD;
    const __nv_bfloat16* Vl = g_vl + (size_t)b * S_ * KVE + h * HD;

    // Q tiles: 64 rows x 8 chunks of 16B, two planes
    #pragma unroll
    for (int i = tid; i < 512; i += 128) {
        int r = i >> 3, c = (i & 7) * 16;
        cpa16(sQhB + (uint32_t)(r * 144 + c), Qh + (size_t)r * D_ + c / 2);
        cpa16(sQlB + (uint32_t)(r * 144 + c), Ql + (size_t)r * D_ + c / 2);
    }
    // K tiles: 256 rows x 8 chunks, two planes
    #pragma unroll
    for (int i = tid; i < 2048; i += 128) {
        int r = i >> 3, c = (i & 7) * 16;
        cpa16(sKVhB + (uint32_t)(r * 144 + c), Kh + (size_t)r * KVE + c / 2);
        cpa16(sKVlB + (uint32_t)(r * 144 + c), Kl + (size_t)r * KVE + c / 2);
    }
    CP_COMMIT;
    CP_WAIT0;
    __syncthreads();

    int arow = w * 16 + (lane & 15);
    int acb  = (lane & 16) >> 1;
    uint32_t qhf[4][4], qlf[4][4];
    #pragma unroll
    for (int kt = 0; kt < 4; kt++) {
        uint32_t off = (uint32_t)((arow * 72 + kt * 16 + acb) * 2);
        ldsm4(qhf[kt], sQhB + off);
        ldsm4(qlf[kt], sQlB + off);
    }

    float c[32][4];
    #pragma unroll
    for (int i = 0; i < 32; i++)
        #pragma unroll
        for (int j = 0; j < 4; j++) c[i][j] = 0.f;

    int brow = (lane & 7) + ((lane & 16) >> 1);
    int bcol = lane & 8;
    #pragma unroll
    for (int np = 0; np < 16; np++) {
        #pragma unroll
        for (int kt = 0; kt < 4; kt++) {
            uint32_t off = (uint32_t)(((np * 16 + brow) * 72 + kt * 16 + bcol) * 2);
            uint32_t bh[4], bl[4];
            ldsm4(bh, sKVhB + off);
            ldsm4(bl, sKVlB + off);
            mma_bf16(c[2*np  ], qhf[kt], bh[0], bh[1]);
            mma_bf16(c[2*np  ], qhf[kt], bl[0], bl[1]);
            mma_bf16(c[2*np  ], qlf[kt], bh[0], bh[1]);
            mma_bf16(c[2*np+1], qhf[kt], bh[2], bh[3]);
            mma_bf16(c[2*np+1], qhf[kt], bl[2], bl[3]);
            mma_bf16(c[2*np+1], qlf[kt], bh[2], bh[3]);
        }
    }
    __syncthreads();   // all warps done reading K smem

    // prefetch V (overwrites K buffers) while doing register softmax
    #pragma unroll
    for (int i = tid; i < 2048; i += 128) {
        int r = i >> 3, cc = (i & 7) * 16;
        cpa16(sKVhB + (uint32_t)(r * 144 + cc), Vh + (size_t)r * KVE + cc / 2);
        cpa16(sKVlB + (uint32_t)(r * 144 + cc), Vl + (size_t)r * KVE + cc / 2);
    }
    CP_COMMIT;

    float mx0 = -1e30f, mx1 = -1e30f;
    #pragma unroll
    for (int nt = 0; nt < 32; nt++) {
        mx0 = fmaxf(mx0, fmaxf(c[nt][0], c[nt][1]));
        mx1 = fmaxf(mx1, fmaxf(c[nt][2], c[nt][3]));
    }
    mx0 = fmaxf(mx0, __shfl_xor_sync(0xffffffffu, mx0, 1));
    mx0 = fmaxf(mx0, __shfl_xor_sync(0xffffffffu, mx0, 2));
    mx1 = fmaxf(mx1, __shfl_xor_sync(0xffffffffu, mx1, 1));
    mx1 = fmaxf(mx1, __shfl_xor_sync(0xffffffffu, mx1, 2));
    float s0 = 0.f, s1 = 0.f;
    #pragma unroll
    for (int nt = 0; nt < 32; nt++) {
        c[nt][0] = __expf(c[nt][0] - mx0); s0 += c[nt][0];
        c[nt][1] = __expf(c[nt][1] - mx0); s0 += c[nt][1];
        c[nt][2] = __expf(c[nt][2] - mx1); s1 += c[nt][2];
        c[nt][3] = __expf(c[nt][3] - mx1); s1 += c[nt][3];
    }
    s0 += __shfl_xor_sync(0xffffffffu, s0, 1);
    s0 += __shfl_xor_sync(0xffffffffu, s0, 2);
    s1 += __shfl_xor_sync(0xffffffffu, s1, 1);
    s1 += __shfl_xor_sync(0xffffffffu, s1, 2);
    float i0 = 1.0f / s0, i1 = 1.0f / s1;
    #pragma unroll
    for (int nt = 0; nt < 32; nt++) {
        c[nt][0] *= i0; c[nt][1] *= i0; c[nt][2] *= i1; c[nt][3] *= i1;
    }
    CP_WAIT0;
    __syncthreads();   // V ready

    float o[8][4];
    #pragma unroll
    for (int i = 0; i < 8; i++)
        #pragma unroll
        for (int j = 0; j < 4; j++) o[i][j] = 0.f;

    int vrow = (lane & 7) + (lane & 8);
    int vcb  = (lane & 16) >> 1;
    #pragma unroll
    for (int kt = 0; kt < 16; kt++) {
        uint32_t phi[4], plo[4];
        phi[0] = pack_hl(c[2*kt  ][0], c[2*kt  ][1], plo[0]);
        phi[1] = pack_hl(c[2*kt  ][2], c[2*kt  ][3], plo[1]);
        phi[2] = pack_hl(c[2*kt+1][0], c[2*kt+1][1], plo[2]);
        phi[3] = pack_hl(c[2*kt+1][2], c[2*kt+1][3], plo[3]);
        #pragma unroll
        for (int dp = 0; dp < 4; dp++) {
            uint32_t off = (uint32_t)(((kt * 16 + vrow) * 72 + dp * 16 + vcb) * 2);
            uint32_t bh[4], bl[4];
            ldsm4t(bh, sKVhB + off);
            ldsm4t(bl, sKVlB + off);
            mma_bf16(o[2*dp  ], phi, bh[0], bh[1]);
            mma_bf16(o[2*dp  ], phi, bl[0], bl[1]);
            mma_bf16(o[2*dp  ], plo, bh[0], bh[1]);
            mma_bf16(o[2*dp+1], phi, bh[2], bh[3]);
            mma_bf16(o[2*dp+1], phi, bl[2], bl[3]);
            mma_bf16(o[2*dp+1], plo, bh[2], bh[3]);
        }
    }

    float* Ob = g_att + ((size_t)(b * N_ + qt * 64 + w * 16 + (lane >> 2))) * D_ + qh * HD;
    #pragma unroll
    for (int nt = 0; nt < 8; nt++) {
        int col = nt * 8 + (lane & 3) * 2;
        *(float2*)(Ob + col)          = make_float2(o[nt][0], o[nt][1]);
        *(float2*)(Ob + 8 * D_ + col) = make_float2(o[nt][2], o[nt][3]);
    }
}

// ---------------- launch ----------------------------------------------------
extern "C" void kernel_launch(void* const* d_in, const int* in_sizes, int n_in,
                              void* d_out, int out_size) {
    const float* x  = (const float*)d_in[0];
    const float* y  = (const float*)d_in[1];
    const float* wq = (const float*)d_in[2];
    const float* wk = (const float*)d_in[3];
    const float* wv = (const float*)d_in[4];
    const float* wo = (const float*)d_in[5];
    const float* gamma = (const float*)d_in[6];
    const float* beta  = (const float*)d_in[7];
    float* out = (float*)d_out;

    cudaFuncSetAttribute(attn_mma_kernel,
                         cudaFuncAttributeMaxDynamicSharedMemorySize, ATT_SMEM);
    cudaFuncSetAttribute(gemm_q_kernel,  cudaFuncAttributeMaxDynamicSharedMemorySize, G_SMEM4);
    cudaFuncSetAttribute(gemm_kv_kernel, cudaFuncAttributeMaxDynamicSharedMemorySize, G_SMEM4);
    cudaFuncSetAttribute(gemm_o_kernel,  cudaFuncAttributeMaxDynamicSharedMemorySize, G_SMEM4);

    absmean_all_kernel<<<dim3(256, 4), 256>>>(wq, wk, wv, wo);
    reduce_kernel<<<4, 256>>>();
    wquant_all_kernel<<<dim3(512, 4), 256>>>(wq, wk, wv, wo);

    act_quant_kernel<<<B_ * N_ + B_ * S_, 256>>>(x, y);

    gemm_q_kernel<<<dim3(8, 128), 256, G_SMEM4>>>();
    gemm_kv_kernel<<<dim3(4, 32, 2), 256, G_SMEM4>>>();

    attn_mma_kernel<<<B_ * HQ * (N_ / 64), 128, ATT_SMEM>>>();

    ln_quant_kernel<<<B_ * N_, 256>>>(gamma, beta);
    gemm_o_kernel<<<dim3(8, 128), 256, G_SMEM4>>>(out);
}